// round 6
// baseline (speedup 1.0000x reference)
#include <cuda_runtime.h>
#include <stdint.h>
#include <math.h>

#define SEQ   1024
#define HEADS 12
#define BATCH 16
#define DH    64
#define DIM   768
#define BHT   (BATCH*HEADS)   // 192
#define LOG2E 1.4426950408889634f

// pre-converted operands + attention scratch (tf32 bits stored as unsigned)
__device__ unsigned g_x32[(size_t)BATCH*SEQ*DIM];
__device__ unsigned g_w32[(size_t)3*DIM*DIM];
__device__ float    g_bL2[(size_t)SEQ*SEQ];          // bias * log2e
__device__ unsigned g_q[(size_t)BHT*SEQ*DH];
__device__ unsigned g_k[(size_t)BHT*SEQ*DH];
__device__ unsigned g_v[(size_t)BHT*DH*SEQ];         // TRANSPOSED: [bh][chan][key]

__device__ __forceinline__ unsigned f2tf(float f) {
    unsigned r;
    asm("cvt.rna.tf32.f32 %0, %1;" : "=r"(r) : "f"(f));
    return r;
}
__device__ __forceinline__ float ex2(float x) {
    float r;
    asm("ex2.approx.f32 %0, %1;" : "=f"(r) : "f"(x));
    return r;
}
__device__ __forceinline__ uint32_t s2u(const void* p) {
    return (uint32_t)__cvta_generic_to_shared(p);
}
__device__ __forceinline__ void ldsm4(unsigned r[4], uint32_t a) {
    asm volatile("ldmatrix.sync.aligned.m8n8.x4.shared.b16 {%0,%1,%2,%3}, [%4];"
                 : "=r"(r[0]), "=r"(r[1]), "=r"(r[2]), "=r"(r[3]) : "r"(a));
}
__device__ __forceinline__ void mma_tf32(float c[4], const unsigned a[4], const unsigned b[2]) {
    asm volatile("mma.sync.aligned.m16n8k8.row.col.f32.tf32.tf32.f32 "
                 "{%0,%1,%2,%3}, {%4,%5,%6,%7}, {%8,%9}, {%0,%1,%2,%3};"
                 : "+f"(c[0]), "+f"(c[1]), "+f"(c[2]), "+f"(c[3])
                 : "r"(a[0]), "r"(a[1]), "r"(a[2]), "r"(a[3]),
                   "r"(b[0]), "r"(b[1]));
}
__device__ __forceinline__ void cp16(uint32_t s, const void* g) {
    asm volatile("cp.async.ca.shared.global [%0], [%1], 16;" :: "r"(s), "l"(g));
}

// ---------------------------------------------------------------------------
// Kernel 0: one-shot input conversion (x, w -> tf32; bias -> bias*log2e)
// ---------------------------------------------------------------------------
#define NX (BATCH*SEQ*DIM)
#define NW (3*DIM*DIM)
#define NB (SEQ*SEQ)
#define CVT_BLOCKS ((NX+NW+NB)/4/256)

__global__ __launch_bounds__(256) void cvt_inputs(const float* __restrict__ x,
                                                  const float* __restrict__ w,
                                                  const float* __restrict__ bias) {
    size_t i = ((size_t)blockIdx.x * 256 + threadIdx.x) * 4;
    if (i < NX) {
        float4 v = *(const float4*)(x + i);
        *(uint4*)(g_x32 + i) = make_uint4(f2tf(v.x), f2tf(v.y), f2tf(v.z), f2tf(v.w));
    } else if (i < NX + NW) {
        size_t j = i - NX;
        float4 v = *(const float4*)(w + j);
        *(uint4*)(g_w32 + j) = make_uint4(f2tf(v.x), f2tf(v.y), f2tf(v.z), f2tf(v.w));
    } else {
        size_t j = i - NX - NW;
        float4 v = *(const float4*)(bias + j);
        *(float4*)(g_bL2 + j) = make_float4(v.x * LOG2E, v.y * LOG2E, v.z * LOG2E, v.w * LOG2E);
    }
}

// ---------------------------------------------------------------------------
// Kernel 1: qkv = x @ w^T + b  (tf32, pre-converted operands, cp.async pipe)
// ---------------------------------------------------------------------------
#define LDA 36
#define TILE_W (128 * LDA)
#define QKV_SMEM (4 * TILE_W * 4)          // 73728 B

__global__ __launch_bounds__(256) void qkv_gemm(const float* __restrict__ bq) {
    extern __shared__ unsigned qsm[];
    const uint32_t smb = s2u(qsm);

    const int tid  = threadIdx.x;
    const int warp = tid >> 5;
    const int lane = tid & 31;
    const int r0   = lane >> 2;
    const int qq   = lane & 3;
    const int g    = lane >> 3;
    const int lr   = lane & 7;
    const int m_w  = (warp >> 1) * 32;
    const int n_w  = (warp & 1) * 64;

    float C[2][8][4];
#pragma unroll
    for (int i = 0; i < 2; i++)
#pragma unroll
        for (int j = 0; j < 8; j++)
#pragma unroll
            for (int k = 0; k < 4; k++) C[i][j][k] = 0.f;

    const unsigned* Ag = g_x32 + (size_t)(blockIdx.y * 128) * DIM;
    const unsigned* Bg = g_w32 + (size_t)(blockIdx.x * 128) * DIM;

    const int lr8 = tid >> 3;
    const int lc4 = (tid & 7) * 4;

    const uint32_t aoff = (uint32_t)(((m_w + (g & 1) * 8 + lr) * LDA + (g >> 1) * 4) * 4);
    const uint32_t boff = (uint32_t)(((n_w + (g >> 1) * 8 + lr) * LDA + (g & 1) * 4) * 4);

#define QKV_ISSUE(IT, BUF) do {                                                   \
    uint32_t ab = smb + (BUF) * (uint32_t)(TILE_W * 4);                           \
    uint32_t bb_ = smb + (uint32_t)(2 * TILE_W * 4) + (BUF) * (uint32_t)(TILE_W * 4); \
    _Pragma("unroll")                                                             \
    for (int i = 0; i < 4; i++) {                                                 \
        int r = lr8 + i * 32;                                                     \
        cp16(ab  + (uint32_t)((r * LDA + lc4) * 4), Ag + (size_t)r * DIM + (IT) * 32 + lc4); \
        cp16(bb_ + (uint32_t)((r * LDA + lc4) * 4), Bg + (size_t)r * DIM + (IT) * 32 + lc4); \
    } } while (0)

    QKV_ISSUE(0, 0);
    asm volatile("cp.async.commit_group;");
    QKV_ISSUE(1, 1);
    asm volatile("cp.async.commit_group;");

    for (int it = 0; it < 24; it++) {
        if (it < 23) asm volatile("cp.async.wait_group 1;");
        else         asm volatile("cp.async.wait_group 0;");
        __syncthreads();

        const uint32_t Ab = smb + (it & 1) * (uint32_t)(TILE_W * 4) + aoff;
        const uint32_t Bb = smb + (uint32_t)(2 * TILE_W * 4) + (it & 1) * (uint32_t)(TILE_W * 4) + boff;
#pragma unroll
        for (int ks = 0; ks < 4; ks++) {
            unsigned a[2][4];
#pragma unroll
            for (int mt = 0; mt < 2; mt++)
                ldsm4(a[mt], Ab + mt * (uint32_t)(16 * LDA * 4) + ks * 32);
#pragma unroll
            for (int ntp = 0; ntp < 4; ntp++) {
                unsigned bf[4];
                ldsm4(bf, Bb + ntp * (uint32_t)(16 * LDA * 4) + ks * 32);
#pragma unroll
                for (int mt = 0; mt < 2; mt++) {
                    mma_tf32(C[mt][2 * ntp], a[mt], bf);
                    mma_tf32(C[mt][2 * ntp + 1], a[mt], bf + 2);
                }
            }
        }
        __syncthreads();
        if (it + 2 < 24) {
            QKV_ISSUE(it + 2, it & 1);
            asm volatile("cp.async.commit_group;");
        }
    }

    // epilogue: bias add, tf32 round, scatter (q/k row-major, v transposed)
#pragma unroll
    for (int nt = 0; nt < 8; nt++) {
        int nb = blockIdx.x * 128 + n_w + nt * 8 + 2 * qq;
        float2 bb = *(const float2*)(bq + nb);
        int which = nb / DIM;
        int hn    = nb % DIM;
        int h     = hn >> 6;
        int c0    = hn & 63;
#pragma unroll
        for (int mt = 0; mt < 2; mt++) {
#pragma unroll
            for (int half = 0; half < 2; half++) {
                int m = blockIdx.y * 128 + m_w + mt * 16 + r0 + half * 8;
                int b = m >> 10, s = m & 1023;
                unsigned u0 = f2tf(C[mt][nt][2 * half + 0] + bb.x);
                unsigned u1 = f2tf(C[mt][nt][2 * half + 1] + bb.y);
                size_t bh = (size_t)(b * HEADS + h);
                if (which == 0) {
                    *(uint2*)(g_q + (bh * SEQ + s) * DH + c0) = make_uint2(u0, u1);
                } else if (which == 1) {
                    *(uint2*)(g_k + (bh * SEQ + s) * DH + c0) = make_uint2(u0, u1);
                } else {
                    size_t vb = bh * DH * SEQ;
                    g_v[vb + (size_t)c0 * SEQ + s]       = u0;
                    g_v[vb + (size_t)(c0 + 1) * SEQ + s] = u1;
                }
            }
        }
    }
#undef QKV_ISSUE
}

// ---------------------------------------------------------------------------
// Kernel 2: flash attention. 512 threads / 16 warps, BM=256 (16 rows/warp),
// BN=64 keys/iter. Q fragments in registers; P in registers via shuffles;
// K/V triple-buffered cp.async. 4 warps/SMSP for latency hiding.
// ---------------------------------------------------------------------------
#define QS    68
#define TILEW (64 * QS)
#define AT_SMEM (6 * TILEW * 4)            // 104448 B (Q staging aliases tiles)

__global__ __launch_bounds__(512, 1) void attn_kernel(const float* __restrict__ dsc,
                                                      float* __restrict__ out) {
    extern __shared__ unsigned smu[];
    const uint32_t smb = s2u(smu);

    const int tid  = threadIdx.x;
    const int warp = tid >> 5;
    const int lane = tid & 31;
    const int r0   = lane >> 2;
    const int q    = lane & 3;
    const int g    = lane >> 3;
    const int lr   = lane & 7;
    const int wm   = warp * 16;

    const int bh = blockIdx.y;
    const int q0 = blockIdx.x * 256;
    const int b  = bh / HEADS;
    const int h  = bh % HEADS;

    const unsigned* qg = g_q + ((size_t)bh * SEQ + q0) * DH;
    const unsigned* kg = g_k + (size_t)bh * SEQ * DH;
    const unsigned* vg = g_v + (size_t)bh * DH * SEQ;

    // ---- stage Q tile (256x64) into smem, pull fragments into registers ----
#pragma unroll
    for (int i = 0; i < 8; i++) {
        int id = tid + i * 512;
        int r  = id >> 4;
        int c  = (id & 15) * 4;
        *(uint4*)&smu[r * QS + c] = *(const uint4*)(qg + (size_t)r * DH + c);
    }
    __syncthreads();

    unsigned Qf[8][4];
    {
        uint32_t qA = smb + (uint32_t)(((wm + (g & 1) * 8 + lr) * QS + (g >> 1) * 4) * 4);
#pragma unroll
        for (int ks = 0; ks < 8; ks++)
            ldsm4(Qf[ks], qA + ks * 32);
    }
    __syncthreads();   // staging region becomes K/V buffers now

    // cp.async mapping: 512 threads, 2 chunks per tile each
    const int cr  = tid >> 4;        // row 0..31 (+32 per round)
    const int cc  = (tid & 15) * 4;  // word col

#define AT_ISSUE(T, J) do {                                                       \
    uint32_t kb = smb + (uint32_t)((2 * (J)) * TILEW * 4);                        \
    uint32_t vb = smb + (uint32_t)((2 * (J) + 1) * TILEW * 4);                    \
    _Pragma("unroll")                                                             \
    for (int i = 0; i < 2; i++) {                                                 \
        int r = cr + i * 32;                                                      \
        cp16(kb + (uint32_t)((r * QS + cc) * 4), kg + (size_t)((T) * 64 + r) * DH + cc); \
        cp16(vb + (uint32_t)((r * QS + cc) * 4), vg + (size_t)r * SEQ + (T) * 64 + cc);  \
    } } while (0)

    AT_ISSUE(0, 0);
    asm volatile("cp.async.commit_group;");
    AT_ISSUE(1, 1);
    asm volatile("cp.async.commit_group;");

    float O[8][4];
#pragma unroll
    for (int nt = 0; nt < 8; nt++)
#pragma unroll
        for (int k = 0; k < 4; k++) O[nt][k] = 0.f;
    float m_lo = -1e30f, m_hi = -1e30f, l_lo = 0.f, l_hi = 0.f;

    const float scale = 0.125f * LOG2E;
    const unsigned srcA = (lane & ~3u) | ((unsigned)q >> 1);
    const unsigned srcB = srcA | 2u;
    const bool odd = (q & 1);

    const uint32_t fragoff = (uint32_t)((((g >> 1) * 8 + lr) * QS + (g & 1) * 4) * 4);

    for (int t = 0; t < 16; t++) {
        if (t < 15) asm volatile("cp.async.wait_group 1;");
        else        asm volatile("cp.async.wait_group 0;");
        __syncthreads();
        if (t + 2 < 16) {
            AT_ISSUE(t + 2, (t + 2) % 3);
            asm volatile("cp.async.commit_group;");
        }
        const int j = t % 3;
        const uint32_t kB = smb + (uint32_t)((2 * j) * TILEW * 4) + fragoff;
        const uint32_t vB = smb + (uint32_t)((2 * j + 1) * TILEW * 4) + fragoff;

        // ---- S = Q K^T  (per warp: 16 x 64) ----
        float S[8][4];
#pragma unroll
        for (int nt = 0; nt < 8; nt++)
#pragma unroll
            for (int k = 0; k < 4; k++) S[nt][k] = 0.f;

#pragma unroll
        for (int ks = 0; ks < 8; ks++) {
#pragma unroll
            for (int ntp = 0; ntp < 4; ntp++) {
                unsigned bf[4];
                ldsm4(bf, kB + ntp * (uint32_t)(16 * QS * 4) + ks * 32);
                mma_tf32(S[2 * ntp], Qf[ks], bf);
                mma_tf32(S[2 * ntp + 1], Qf[ks], bf + 2);
            }
        }

        // ---- scale + bias (log2 domain), online softmax ----
        const float* b_lo = g_bL2 + (size_t)(q0 + wm + r0) * SEQ + t * 64;
        const float* b_hi = b_lo + 8 * SEQ;
        float mlo = -1e30f, mhi = -1e30f;
#pragma unroll
        for (int nt = 0; nt < 8; nt++) {
            float2 bb0 = *(const float2*)(b_lo + nt * 8 + 2 * q);
            float2 bb1 = *(const float2*)(b_hi + nt * 8 + 2 * q);
            S[nt][0] = S[nt][0] * scale + bb0.x;
            S[nt][1] = S[nt][1] * scale + bb0.y;
            S[nt][2] = S[nt][2] * scale + bb1.x;
            S[nt][3] = S[nt][3] * scale + bb1.y;
            mlo = fmaxf(mlo, fmaxf(S[nt][0], S[nt][1]));
            mhi = fmaxf(mhi, fmaxf(S[nt][2], S[nt][3]));
        }
        mlo = fmaxf(mlo, __shfl_xor_sync(0xffffffffu, mlo, 1));
        mlo = fmaxf(mlo, __shfl_xor_sync(0xffffffffu, mlo, 2));
        mhi = fmaxf(mhi, __shfl_xor_sync(0xffffffffu, mhi, 1));
        mhi = fmaxf(mhi, __shfl_xor_sync(0xffffffffu, mhi, 2));

        float mn_lo = fmaxf(m_lo, mlo);
        float mn_hi = fmaxf(m_hi, mhi);
        float f_lo  = ex2(m_lo - mn_lo);
        float f_hi  = ex2(m_hi - mn_hi);
        m_lo = mn_lo; m_hi = mn_hi;

        float rlo = 0.f, rhi = 0.f;
#pragma unroll
        for (int nt = 0; nt < 8; nt++) {
            S[nt][0] = ex2(S[nt][0] - mn_lo);
            S[nt][1] = ex2(S[nt][1] - mn_lo);
            S[nt][2] = ex2(S[nt][2] - mn_hi);
            S[nt][3] = ex2(S[nt][3] - mn_hi);
            rlo += S[nt][0] + S[nt][1];
            rhi += S[nt][2] + S[nt][3];
        }
        rlo += __shfl_xor_sync(0xffffffffu, rlo, 1);
        rlo += __shfl_xor_sync(0xffffffffu, rlo, 2);
        rhi += __shfl_xor_sync(0xffffffffu, rhi, 1);
        rhi += __shfl_xor_sync(0xffffffffu, rhi, 2);
        l_lo = l_lo * f_lo + rlo;
        l_hi = l_hi * f_hi + rhi;

#pragma unroll
        for (int nt = 0; nt < 8; nt++) {
            O[nt][0] *= f_lo; O[nt][1] *= f_lo;
            O[nt][2] *= f_hi; O[nt][3] *= f_hi;
        }

        // ---- O += P @ V ; P A-fragments via 4-lane shuffles of S regs ----
#pragma unroll
        for (int ks = 0; ks < 8; ks++) {
            unsigned aP[4];
            {
                float s0 = S[ks][0], s1 = S[ks][1];
                float s2 = S[ks][2], s3 = S[ks][3];
                float v0a = __shfl_sync(0xffffffffu, s0, srcA);
                float v1a = __shfl_sync(0xffffffffu, s1, srcA);
                float v2a = __shfl_sync(0xffffffffu, s2, srcA);
                float v3a = __shfl_sync(0xffffffffu, s3, srcA);
                float v0b = __shfl_sync(0xffffffffu, s0, srcB);
                float v1b = __shfl_sync(0xffffffffu, s1, srcB);
                float v2b = __shfl_sync(0xffffffffu, s2, srcB);
                float v3b = __shfl_sync(0xffffffffu, s3, srcB);
                aP[0] = f2tf(odd ? v1a : v0a);   // (r0,   q)
                aP[1] = f2tf(odd ? v3a : v2a);   // (r0+8, q)
                aP[2] = f2tf(odd ? v1b : v0b);   // (r0,   q+4)
                aP[3] = f2tf(odd ? v3b : v2b);   // (r0+8, q+4)
            }
#pragma unroll
            for (int ntp = 0; ntp < 4; ntp++) {
                unsigned bf[4];
                ldsm4(bf, vB + ntp * (uint32_t)(16 * QS * 4) + ks * 32);
                mma_tf32(O[2 * ntp], aP, bf);
                mma_tf32(O[2 * ntp + 1], aP, bf + 2);
            }
        }
    }

    // ---- epilogue: out[b, row, h*64 + c] = d[row]/l * O ----
    {
        int row_lo = q0 + wm + r0;
        int row_hi = row_lo + 8;
        float sc_lo = dsc[row_lo] / l_lo;
        float sc_hi = dsc[row_hi] / l_hi;
        float* o_lo = out + ((size_t)b * SEQ + row_lo) * DIM + h * DH;
        float* o_hi = out + ((size_t)b * SEQ + row_hi) * DIM + h * DH;
#pragma unroll
        for (int nt = 0; nt < 8; nt++) {
            int c = nt * 8 + 2 * q;
            *(float2*)(o_lo + c) = make_float2(O[nt][0] * sc_lo, O[nt][1] * sc_lo);
            *(float2*)(o_hi + c) = make_float2(O[nt][2] * sc_hi, O[nt][3] * sc_hi);
        }
    }
#undef AT_ISSUE
}

// ---------------------------------------------------------------------------
extern "C" void kernel_launch(void* const* d_in, const int* in_sizes, int n_in,
                              void* d_out, int out_size) {
    const float* x    = (const float*)d_in[0];
    const float* w    = (const float*)d_in[1];
    const float* bq   = (const float*)d_in[2];
    const float* dsc  = (const float*)d_in[3];
    const float* bias = (const float*)d_in[4];
    float* out = (float*)d_out;

    cudaFuncSetAttribute(qkv_gemm, cudaFuncAttributeMaxDynamicSharedMemorySize, QKV_SMEM);
    cudaFuncSetAttribute(attn_kernel, cudaFuncAttributeMaxDynamicSharedMemorySize, AT_SMEM);

    cvt_inputs<<<CVT_BLOCKS, 256>>>(x, w, bias);
    qkv_gemm<<<dim3(18, 128), 256, QKV_SMEM>>>(bq);
    attn_kernel<<<dim3(4, BHT), 512, AT_SMEM>>>(dsc, out);
}

// round 7
// speedup vs baseline: 1.6762x; 1.6762x over previous
#include <cuda_runtime.h>
#include <cuda_fp16.h>
#include <stdint.h>
#include <math.h>

#define SEQ   1024
#define HEADS 12
#define BATCH 16
#define DH    64
#define DIM   768
#define BHT   (BATCH*HEADS)   // 192
#define LOG2E 1.4426950408889634f

// fp16 operands + attention scratch
__device__ __half g_x16[(size_t)BATCH*SEQ*DIM];
__device__ __half g_w16[(size_t)3*DIM*DIM];
__device__ float  g_bL2[(size_t)SEQ*SEQ];            // bias * log2e (fp32)
__device__ __half g_q[(size_t)BHT*SEQ*DH];
__device__ __half g_k[(size_t)BHT*SEQ*DH];
__device__ __half g_v[(size_t)BHT*DH*SEQ];           // TRANSPOSED: [bh][chan][key]

__device__ __forceinline__ float ex2(float x) {
    float r;
    asm("ex2.approx.f32 %0, %1;" : "=f"(r) : "f"(x));
    return r;
}
__device__ __forceinline__ uint32_t s2u(const void* p) {
    return (uint32_t)__cvta_generic_to_shared(p);
}
__device__ __forceinline__ unsigned h2u(__half2 h) {
    return *(unsigned*)&h;
}
__device__ __forceinline__ void ldsm4(unsigned r[4], uint32_t a) {
    asm volatile("ldmatrix.sync.aligned.m8n8.x4.shared.b16 {%0,%1,%2,%3}, [%4];"
                 : "=r"(r[0]), "=r"(r[1]), "=r"(r[2]), "=r"(r[3]) : "r"(a));
}
__device__ __forceinline__ void mma_f16(float c[4], const unsigned a[4],
                                        unsigned b0, unsigned b1) {
    asm volatile("mma.sync.aligned.m16n8k16.row.col.f32.f16.f16.f32 "
                 "{%0,%1,%2,%3}, {%4,%5,%6,%7}, {%8,%9}, {%0,%1,%2,%3};"
                 : "+f"(c[0]), "+f"(c[1]), "+f"(c[2]), "+f"(c[3])
                 : "r"(a[0]), "r"(a[1]), "r"(a[2]), "r"(a[3]),
                   "r"(b0), "r"(b1));
}
__device__ __forceinline__ void cp16(uint32_t s, const void* g) {
    asm volatile("cp.async.ca.shared.global [%0], [%1], 16;" :: "r"(s), "l"(g));
}

// ---------------------------------------------------------------------------
// Kernel 0: one-shot conversion (x, w -> fp16; bias -> bias*log2e fp32)
// ---------------------------------------------------------------------------
#define NX (BATCH*SEQ*DIM)
#define NW (3*DIM*DIM)
#define NB (SEQ*SEQ)
#define CVT_BLOCKS ((NX+NW+NB)/4/256)

__global__ __launch_bounds__(256) void cvt_inputs(const float* __restrict__ x,
                                                  const float* __restrict__ w,
                                                  const float* __restrict__ bias) {
    size_t i = ((size_t)blockIdx.x * 256 + threadIdx.x) * 4;
    if (i < NX) {
        float4 v = *(const float4*)(x + i);
        *(__half2*)(g_x16 + i)     = __floats2half2_rn(v.x, v.y);
        *(__half2*)(g_x16 + i + 2) = __floats2half2_rn(v.z, v.w);
    } else if (i < NX + NW) {
        size_t j = i - NX;
        float4 v = *(const float4*)(w + j);
        *(__half2*)(g_w16 + j)     = __floats2half2_rn(v.x, v.y);
        *(__half2*)(g_w16 + j + 2) = __floats2half2_rn(v.z, v.w);
    } else {
        size_t j = i - NX - NW;
        float4 v = *(const float4*)(bias + j);
        *(float4*)(g_bL2 + j) = make_float4(v.x * LOG2E, v.y * LOG2E, v.z * LOG2E, v.w * LOG2E);
    }
}

// ---------------------------------------------------------------------------
// Kernel 1: qkv = x @ w^T + b  (fp16 m16n8k16, cp.async double-buffer)
// C tile 128x128, BK=64, 8 warps, each warp 32x64.
// smem tiles [128 rows][72 halves] (stride 144 B -> conflict-free ldmatrix).
// ---------------------------------------------------------------------------
#define LDH   72
#define HTILE (128 * LDH)                  // halves per tile
#define QKV_SMEM (4 * HTILE * 2)           // 2 bufs x (A,B) = 73728 B

__global__ __launch_bounds__(256) void qkv_gemm(const float* __restrict__ bq) {
    extern __shared__ __half qsm[];
    const uint32_t smb = s2u(qsm);

    const int tid  = threadIdx.x;
    const int warp = tid >> 5;
    const int lane = tid & 31;
    const int r0   = lane >> 2;
    const int qq   = lane & 3;
    const int g    = lane >> 3;
    const int lr   = lane & 7;
    const int m_w  = (warp >> 1) * 32;
    const int n_w  = (warp & 1) * 64;

    float C[2][8][4];
#pragma unroll
    for (int i = 0; i < 2; i++)
#pragma unroll
        for (int j = 0; j < 8; j++)
#pragma unroll
            for (int k = 0; k < 4; k++) C[i][j][k] = 0.f;

    const __half* Ag = g_x16 + (size_t)(blockIdx.y * 128) * DIM;
    const __half* Bg = g_w16 + (size_t)(blockIdx.x * 128) * DIM;

    const int cr = tid >> 3;             // 0..31 (+32 per round)
    const int cc = (tid & 7) * 8;        // half col (8 halves = 16B)

    const uint32_t aoff = (uint32_t)((m_w + (g & 1) * 8 + lr) * 144 + (g >> 1) * 16);
    const uint32_t boff = (uint32_t)((n_w + (g & 1) * 8 + lr) * 144 + (g >> 1) * 16);

#define QKV_ISSUE(IT, BUF) do {                                                   \
    uint32_t ab = smb + (BUF) * (uint32_t)(HTILE * 2);                            \
    uint32_t bb_ = smb + (uint32_t)(2 * HTILE * 2) + (BUF) * (uint32_t)(HTILE * 2); \
    _Pragma("unroll")                                                             \
    for (int i = 0; i < 4; i++) {                                                 \
        int r = cr + i * 32;                                                      \
        cp16(ab  + (uint32_t)(r * 144 + cc * 2), Ag + (size_t)r * DIM + (IT) * 64 + cc); \
        cp16(bb_ + (uint32_t)(r * 144 + cc * 2), Bg + (size_t)r * DIM + (IT) * 64 + cc); \
    } } while (0)

    QKV_ISSUE(0, 0);
    asm volatile("cp.async.commit_group;");
    QKV_ISSUE(1, 1);
    asm volatile("cp.async.commit_group;");

    for (int it = 0; it < 12; it++) {
        if (it < 11) asm volatile("cp.async.wait_group 1;");
        else         asm volatile("cp.async.wait_group 0;");
        __syncthreads();

        const uint32_t Ab = smb + (it & 1) * (uint32_t)(HTILE * 2) + aoff;
        const uint32_t Bb = smb + (uint32_t)(2 * HTILE * 2) + (it & 1) * (uint32_t)(HTILE * 2) + boff;
#pragma unroll
        for (int ks = 0; ks < 4; ks++) {
            unsigned a[2][4];
#pragma unroll
            for (int mt = 0; mt < 2; mt++)
                ldsm4(a[mt], Ab + mt * (uint32_t)(16 * 144) + ks * 32);
#pragma unroll
            for (int np = 0; np < 4; np++) {
                unsigned bf[4];
                ldsm4(bf, Bb + np * (uint32_t)(16 * 144) + ks * 32);
#pragma unroll
                for (int mt = 0; mt < 2; mt++) {
                    mma_f16(C[mt][2 * np],     a[mt], bf[0], bf[2]);
                    mma_f16(C[mt][2 * np + 1], a[mt], bf[1], bf[3]);
                }
            }
        }
        __syncthreads();
        if (it + 2 < 12) {
            QKV_ISSUE(it + 2, it & 1);
            asm volatile("cp.async.commit_group;");
        }
    }

    // epilogue: bias add, fp16 round, scatter (q/k row-major, v transposed)
#pragma unroll
    for (int nt = 0; nt < 8; nt++) {
        int nb = blockIdx.x * 128 + n_w + nt * 8 + 2 * qq;
        float2 bb = *(const float2*)(bq + nb);
        int which = nb / DIM;
        int hn    = nb % DIM;
        int h     = hn >> 6;
        int c0    = hn & 63;
#pragma unroll
        for (int mt = 0; mt < 2; mt++) {
#pragma unroll
            for (int half = 0; half < 2; half++) {
                int m = blockIdx.y * 128 + m_w + mt * 16 + r0 + half * 8;
                int b = m >> 10, s = m & 1023;
                __half2 hv = __floats2half2_rn(C[mt][nt][2 * half + 0] + bb.x,
                                               C[mt][nt][2 * half + 1] + bb.y);
                size_t bh = (size_t)(b * HEADS + h);
                if (which == 0) {
                    *(__half2*)(g_q + (bh * SEQ + s) * DH + c0) = hv;
                } else if (which == 1) {
                    *(__half2*)(g_k + (bh * SEQ + s) * DH + c0) = hv;
                } else {
                    size_t vb = bh * DH * SEQ;
                    g_v[vb + (size_t)c0 * SEQ + s]       = __low2half(hv);
                    g_v[vb + (size_t)(c0 + 1) * SEQ + s] = __high2half(hv);
                }
            }
        }
    }
#undef QKV_ISSUE
}

// ---------------------------------------------------------------------------
// Kernel 2: flash attention, fp16 m16n8k16. 256 threads / 8 warps,
// BM=128 (16 rows/warp), BN=64. Q frags in regs; P packed from S regs
// (no shuffles); K/V triple-buffered cp.async; ~2 CTAs/SM.
// ---------------------------------------------------------------------------
#define TILEH (64 * LDH)                   // halves per K/V tile (9216 B)
#define AT_SMEM (6 * TILEH * 2)            // 55296 B (Q staging aliases tiles)

__global__ __launch_bounds__(256) void attn_kernel(const float* __restrict__ dsc,
                                                   float* __restrict__ out) {
    extern __shared__ __half smh[];
    const uint32_t smb = s2u(smh);

    const int tid  = threadIdx.x;
    const int warp = tid >> 5;
    const int lane = tid & 31;
    const int r0   = lane >> 2;
    const int q    = lane & 3;
    const int g    = lane >> 3;
    const int lr   = lane & 7;
    const int wm   = warp * 16;

    const int bh = blockIdx.y;
    const int q0 = blockIdx.x * 128;
    const int b  = bh / HEADS;
    const int h  = bh % HEADS;

    const __half* qg = g_q + ((size_t)bh * SEQ + q0) * DH;
    const __half* kg = g_k + (size_t)bh * SEQ * DH;
    const __half* vg = g_v + (size_t)bh * DH * SEQ;

    // ---- stage Q tile (128x64 fp16) into smem, pull fragments to regs ----
#pragma unroll
    for (int i = 0; i < 4; i++) {
        int id = tid + i * 256;
        int r  = id >> 3;
        int c  = (id & 7) * 8;
        *(uint4*)&smh[r * LDH + c] = *(const uint4*)(qg + (size_t)r * DH + c);
    }
    __syncthreads();

    unsigned Qf[4][4];
    {
        uint32_t qA = smb + (uint32_t)((wm + (g & 1) * 8 + lr) * 144 + (g >> 1) * 16);
#pragma unroll
        for (int ks = 0; ks < 4; ks++)
            ldsm4(Qf[ks], qA + ks * 32);
    }
    __syncthreads();   // staging region becomes K/V buffers now

    // cp.async: 2 rounds per tile (64 rows x 128 B)
    const int cr = tid >> 3;          // 0..31 (+32)
    const int cc = (tid & 7) * 8;

#define AT_ISSUE(T, J) do {                                                       \
    uint32_t kb = smb + (uint32_t)((2 * (J)) * TILEH * 2);                        \
    uint32_t vb = smb + (uint32_t)((2 * (J) + 1) * TILEH * 2);                    \
    _Pragma("unroll")                                                             \
    for (int i = 0; i < 2; i++) {                                                 \
        int r = cr + i * 32;                                                      \
        cp16(kb + (uint32_t)(r * 144 + cc * 2), kg + (size_t)((T) * 64 + r) * DH + cc); \
        cp16(vb + (uint32_t)(r * 144 + cc * 2), vg + (size_t)r * SEQ + (T) * 64 + cc);  \
    } } while (0)

    AT_ISSUE(0, 0);
    asm volatile("cp.async.commit_group;");
    AT_ISSUE(1, 1);
    asm volatile("cp.async.commit_group;");

    float O[8][4];
#pragma unroll
    for (int nt = 0; nt < 8; nt++)
#pragma unroll
        for (int k = 0; k < 4; k++) O[nt][k] = 0.f;
    float m_lo = -1e30f, m_hi = -1e30f, l_lo = 0.f, l_hi = 0.f;

    const float scale = 0.125f * LOG2E;
    const uint32_t fragoff = (uint32_t)(((g & 1) * 8 + lr) * 144 + (g >> 1) * 16);

    for (int t = 0; t < 16; t++) {
        if (t < 15) asm volatile("cp.async.wait_group 1;");
        else        asm volatile("cp.async.wait_group 0;");
        __syncthreads();
        if (t + 2 < 16) {
            AT_ISSUE(t + 2, (t + 2) % 3);
            asm volatile("cp.async.commit_group;");
        }
        const int j = t % 3;
        const uint32_t kB = smb + (uint32_t)((2 * j) * TILEH * 2) + fragoff;
        const uint32_t vB = smb + (uint32_t)((2 * j + 1) * TILEH * 2) + fragoff;

        // ---- S = Q K^T  (per warp: 16 x 64) ----
        float S[8][4];
#pragma unroll
        for (int nt = 0; nt < 8; nt++)
#pragma unroll
            for (int k = 0; k < 4; k++) S[nt][k] = 0.f;

#pragma unroll
        for (int ks = 0; ks < 4; ks++) {
#pragma unroll
            for (int np = 0; np < 4; np++) {
                unsigned bf[4];
                ldsm4(bf, kB + np * (uint32_t)(16 * 144) + ks * 32);
                mma_f16(S[2 * np],     Qf[ks], bf[0], bf[2]);
                mma_f16(S[2 * np + 1], Qf[ks], bf[1], bf[3]);
            }
        }

        // ---- scale + bias (log2 domain), online softmax ----
        const float* b_lo = g_bL2 + (size_t)(q0 + wm + r0) * SEQ + t * 64;
        const float* b_hi = b_lo + 8 * SEQ;
        float mlo = -1e30f, mhi = -1e30f;
#pragma unroll
        for (int nt = 0; nt < 8; nt++) {
            float2 bb0 = *(const float2*)(b_lo + nt * 8 + 2 * q);
            float2 bb1 = *(const float2*)(b_hi + nt * 8 + 2 * q);
            S[nt][0] = S[nt][0] * scale + bb0.x;
            S[nt][1] = S[nt][1] * scale + bb0.y;
            S[nt][2] = S[nt][2] * scale + bb1.x;
            S[nt][3] = S[nt][3] * scale + bb1.y;
            mlo = fmaxf(mlo, fmaxf(S[nt][0], S[nt][1]));
            mhi = fmaxf(mhi, fmaxf(S[nt][2], S[nt][3]));
        }
        mlo = fmaxf(mlo, __shfl_xor_sync(0xffffffffu, mlo, 1));
        mlo = fmaxf(mlo, __shfl_xor_sync(0xffffffffu, mlo, 2));
        mhi = fmaxf(mhi, __shfl_xor_sync(0xffffffffu, mhi, 1));
        mhi = fmaxf(mhi, __shfl_xor_sync(0xffffffffu, mhi, 2));

        float mn_lo = fmaxf(m_lo, mlo);
        float mn_hi = fmaxf(m_hi, mhi);
        float f_lo  = ex2(m_lo - mn_lo);
        float f_hi  = ex2(m_hi - mn_hi);
        m_lo = mn_lo; m_hi = mn_hi;

        float rlo = 0.f, rhi = 0.f;
#pragma unroll
        for (int nt = 0; nt < 8; nt++) {
            S[nt][0] = ex2(S[nt][0] - mn_lo);
            S[nt][1] = ex2(S[nt][1] - mn_lo);
            S[nt][2] = ex2(S[nt][2] - mn_hi);
            S[nt][3] = ex2(S[nt][3] - mn_hi);
            rlo += S[nt][0] + S[nt][1];
            rhi += S[nt][2] + S[nt][3];
        }
        rlo += __shfl_xor_sync(0xffffffffu, rlo, 1);
        rlo += __shfl_xor_sync(0xffffffffu, rlo, 2);
        rhi += __shfl_xor_sync(0xffffffffu, rhi, 1);
        rhi += __shfl_xor_sync(0xffffffffu, rhi, 2);
        l_lo = l_lo * f_lo + rlo;
        l_hi = l_hi * f_hi + rhi;

#pragma unroll
        for (int nt = 0; nt < 8; nt++) {
            O[nt][0] *= f_lo; O[nt][1] *= f_lo;
            O[nt][2] *= f_hi; O[nt][3] *= f_hi;
        }

        // ---- O += P @ V ; P A-fragments packed directly from S regs ----
#pragma unroll
        for (int ks = 0; ks < 4; ks++) {
            unsigned aP[4];
            aP[0] = h2u(__floats2half2_rn(S[2 * ks][0],     S[2 * ks][1]));
            aP[1] = h2u(__floats2half2_rn(S[2 * ks][2],     S[2 * ks][3]));
            aP[2] = h2u(__floats2half2_rn(S[2 * ks + 1][0], S[2 * ks + 1][1]));
            aP[3] = h2u(__floats2half2_rn(S[2 * ks + 1][2], S[2 * ks + 1][3]));
#pragma unroll
            for (int np = 0; np < 4; np++) {
                unsigned bf[4];
                ldsm4(bf, vB + np * (uint32_t)(16 * 144) + ks * 32);
                mma_f16(O[2 * np],     aP, bf[0], bf[2]);
                mma_f16(O[2 * np + 1], aP, bf[1], bf[3]);
            }
        }
    }

    // ---- epilogue: out[b, row, h*64 + c] = d[row]/l * O ----
    {
        int row_lo = q0 + wm + r0;
        int row_hi = row_lo + 8;
        float sc_lo = dsc[row_lo] / l_lo;
        float sc_hi = dsc[row_hi] / l_hi;
        float* o_lo = out + ((size_t)b * SEQ + row_lo) * DIM + h * DH;
        float* o_hi = out + ((size_t)b * SEQ + row_hi) * DIM + h * DH;
#pragma unroll
        for (int nt = 0; nt < 8; nt++) {
            int c = nt * 8 + 2 * q;
            *(float2*)(o_lo + c) = make_float2(O[nt][0] * sc_lo, O[nt][1] * sc_lo);
            *(float2*)(o_hi + c) = make_float2(O[nt][2] * sc_hi, O[nt][3] * sc_hi);
        }
    }
#undef AT_ISSUE
}

// ---------------------------------------------------------------------------
extern "C" void kernel_launch(void* const* d_in, const int* in_sizes, int n_in,
                              void* d_out, int out_size) {
    const float* x    = (const float*)d_in[0];
    const float* w    = (const float*)d_in[1];
    const float* bq   = (const float*)d_in[2];
    const float* dsc  = (const float*)d_in[3];
    const float* bias = (const float*)d_in[4];
    float* out = (float*)d_out;

    cudaFuncSetAttribute(qkv_gemm, cudaFuncAttributeMaxDynamicSharedMemorySize, QKV_SMEM);
    cudaFuncSetAttribute(attn_kernel, cudaFuncAttributeMaxDynamicSharedMemorySize, AT_SMEM);

    cvt_inputs<<<CVT_BLOCKS, 256>>>(x, w, bias);
    qkv_gemm<<<dim3(18, 128), 256, QKV_SMEM>>>(bq);
    attn_kernel<<<dim3(8, BHT), 256, AT_SMEM>>>(dsc, out);
}

// round 8
// speedup vs baseline: 1.7651x; 1.0531x over previous
#include <cuda_runtime.h>
#include <cuda_fp16.h>
#include <stdint.h>
#include <math.h>

#define SEQ   1024
#define HEADS 12
#define BATCH 16
#define DH    64
#define DIM   768
#define BHT   (BATCH*HEADS)   // 192
#define LOG2E 1.4426950408889634f
#define QSCALE (0.125f * LOG2E)   // folded into stored q

// fp16 operands + attention scratch
__device__ __half g_x16[(size_t)BATCH*SEQ*DIM];
__device__ __half g_w16[(size_t)3*DIM*DIM];
__device__ float  g_bL2[(size_t)SEQ*SEQ];            // bias * log2e (fp32)
__device__ __half g_q[(size_t)BHT*SEQ*DH];           // pre-scaled by 0.125*log2e
__device__ __half g_k[(size_t)BHT*SEQ*DH];
__device__ __half g_v[(size_t)BHT*DH*SEQ];           // TRANSPOSED: [bh][chan][key]

__device__ __forceinline__ float ex2(float x) {
    float r;
    asm("ex2.approx.f32 %0, %1;" : "=f"(r) : "f"(x));
    return r;
}
__device__ __forceinline__ uint32_t s2u(const void* p) {
    return (uint32_t)__cvta_generic_to_shared(p);
}
__device__ __forceinline__ unsigned h2u(__half2 h) {
    return *(unsigned*)&h;
}
__device__ __forceinline__ void ldsm4(unsigned r[4], uint32_t a) {
    asm volatile("ldmatrix.sync.aligned.m8n8.x4.shared.b16 {%0,%1,%2,%3}, [%4];"
                 : "=r"(r[0]), "=r"(r[1]), "=r"(r[2]), "=r"(r[3]) : "r"(a));
}
__device__ __forceinline__ void mma_f16(float c[4], const unsigned a[4],
                                        unsigned b0, unsigned b1) {
    asm volatile("mma.sync.aligned.m16n8k16.row.col.f32.f16.f16.f32 "
                 "{%0,%1,%2,%3}, {%4,%5,%6,%7}, {%8,%9}, {%0,%1,%2,%3};"
                 : "+f"(c[0]), "+f"(c[1]), "+f"(c[2]), "+f"(c[3])
                 : "r"(a[0]), "r"(a[1]), "r"(a[2]), "r"(a[3]),
                   "r"(b0), "r"(b1));
}
__device__ __forceinline__ void cp16(uint32_t s, const void* g) {
    asm volatile("cp.async.ca.shared.global [%0], [%1], 16;" :: "r"(s), "l"(g));
}

// ---------------------------------------------------------------------------
// Kernel 0: one-shot conversion (x, w -> fp16; bias -> bias*log2e fp32)
// ---------------------------------------------------------------------------
#define NX (BATCH*SEQ*DIM)
#define NW (3*DIM*DIM)
#define NB (SEQ*SEQ)
#define CVT_BLOCKS ((NX+NW+NB)/4/256)

__global__ __launch_bounds__(256) void cvt_inputs(const float* __restrict__ x,
                                                  const float* __restrict__ w,
                                                  const float* __restrict__ bias) {
    size_t i = ((size_t)blockIdx.x * 256 + threadIdx.x) * 4;
    if (i < NX) {
        float4 v = *(const float4*)(x + i);
        *(__half2*)(g_x16 + i)     = __floats2half2_rn(v.x, v.y);
        *(__half2*)(g_x16 + i + 2) = __floats2half2_rn(v.z, v.w);
    } else if (i < NX + NW) {
        size_t j = i - NX;
        float4 v = *(const float4*)(w + j);
        *(__half2*)(g_w16 + j)     = __floats2half2_rn(v.x, v.y);
        *(__half2*)(g_w16 + j + 2) = __floats2half2_rn(v.z, v.w);
    } else {
        size_t j = i - NX - NW;
        float4 v = *(const float4*)(bias + j);
        *(float4*)(g_bL2 + j) = make_float4(v.x * LOG2E, v.y * LOG2E, v.z * LOG2E, v.w * LOG2E);
    }
}

// ---------------------------------------------------------------------------
// Kernel 1: qkv = x @ w^T + b  (fp16 m16n8k16, cp.async double-buffer)
// C tile 128x128, BK=64, 8 warps, each warp 32x64.
// Epilogue: q pre-scaled by 0.125*log2e; v stored transposed.
// ---------------------------------------------------------------------------
#define LDH   72
#define HTILE (128 * LDH)
#define QKV_SMEM (4 * HTILE * 2)           // 73728 B

__global__ __launch_bounds__(256) void qkv_gemm(const float* __restrict__ bq) {
    extern __shared__ __half qsm[];
    const uint32_t smb = s2u(qsm);

    const int tid  = threadIdx.x;
    const int warp = tid >> 5;
    const int lane = tid & 31;
    const int r0   = lane >> 2;
    const int qq   = lane & 3;
    const int g    = lane >> 3;
    const int lr   = lane & 7;
    const int m_w  = (warp >> 1) * 32;
    const int n_w  = (warp & 1) * 64;

    float C[2][8][4];
#pragma unroll
    for (int i = 0; i < 2; i++)
#pragma unroll
        for (int j = 0; j < 8; j++)
#pragma unroll
            for (int k = 0; k < 4; k++) C[i][j][k] = 0.f;

    const __half* Ag = g_x16 + (size_t)(blockIdx.y * 128) * DIM;
    const __half* Bg = g_w16 + (size_t)(blockIdx.x * 128) * DIM;

    const int cr = tid >> 3;
    const int cc = (tid & 7) * 8;

    const uint32_t aoff = (uint32_t)((m_w + (g & 1) * 8 + lr) * 144 + (g >> 1) * 16);
    const uint32_t boff = (uint32_t)((n_w + (g & 1) * 8 + lr) * 144 + (g >> 1) * 16);

#define QKV_ISSUE(IT, BUF) do {                                                   \
    uint32_t ab = smb + (BUF) * (uint32_t)(HTILE * 2);                            \
    uint32_t bb_ = smb + (uint32_t)(2 * HTILE * 2) + (BUF) * (uint32_t)(HTILE * 2); \
    _Pragma("unroll")                                                             \
    for (int i = 0; i < 4; i++) {                                                 \
        int r = cr + i * 32;                                                      \
        cp16(ab  + (uint32_t)(r * 144 + cc * 2), Ag + (size_t)r * DIM + (IT) * 64 + cc); \
        cp16(bb_ + (uint32_t)(r * 144 + cc * 2), Bg + (size_t)r * DIM + (IT) * 64 + cc); \
    } } while (0)

    QKV_ISSUE(0, 0);
    asm volatile("cp.async.commit_group;");
    QKV_ISSUE(1, 1);
    asm volatile("cp.async.commit_group;");

    for (int it = 0; it < 12; it++) {
        if (it < 11) asm volatile("cp.async.wait_group 1;");
        else         asm volatile("cp.async.wait_group 0;");
        __syncthreads();

        const uint32_t Ab = smb + (it & 1) * (uint32_t)(HTILE * 2) + aoff;
        const uint32_t Bb = smb + (uint32_t)(2 * HTILE * 2) + (it & 1) * (uint32_t)(HTILE * 2) + boff;
#pragma unroll
        for (int ks = 0; ks < 4; ks++) {
            unsigned a[2][4];
#pragma unroll
            for (int mt = 0; mt < 2; mt++)
                ldsm4(a[mt], Ab + mt * (uint32_t)(16 * 144) + ks * 32);
#pragma unroll
            for (int np = 0; np < 4; np++) {
                unsigned bf[4];
                ldsm4(bf, Bb + np * (uint32_t)(16 * 144) + ks * 32);
#pragma unroll
                for (int mt = 0; mt < 2; mt++) {
                    mma_f16(C[mt][2 * np],     a[mt], bf[0], bf[2]);
                    mma_f16(C[mt][2 * np + 1], a[mt], bf[1], bf[3]);
                }
            }
        }
        __syncthreads();
        if (it + 2 < 12) {
            QKV_ISSUE(it + 2, it & 1);
            asm volatile("cp.async.commit_group;");
        }
    }

    // epilogue: bias add, (q: fold softmax scale), fp16 round, scatter
#pragma unroll
    for (int nt = 0; nt < 8; nt++) {
        int nb = blockIdx.x * 128 + n_w + nt * 8 + 2 * qq;
        float2 bb = *(const float2*)(bq + nb);
        int which = nb / DIM;
        int hn    = nb % DIM;
        int h     = hn >> 6;
        int c0    = hn & 63;
        float sc  = (which == 0) ? QSCALE : 1.0f;
#pragma unroll
        for (int mt = 0; mt < 2; mt++) {
#pragma unroll
            for (int half = 0; half < 2; half++) {
                int m = blockIdx.y * 128 + m_w + mt * 16 + r0 + half * 8;
                int b = m >> 10, s = m & 1023;
                __half2 hv = __floats2half2_rn((C[mt][nt][2 * half + 0] + bb.x) * sc,
                                               (C[mt][nt][2 * half + 1] + bb.y) * sc);
                size_t bh = (size_t)(b * HEADS + h);
                if (which == 0) {
                    *(__half2*)(g_q + (bh * SEQ + s) * DH + c0) = hv;
                } else if (which == 1) {
                    *(__half2*)(g_k + (bh * SEQ + s) * DH + c0) = hv;
                } else {
                    size_t vb = bh * DH * SEQ;
                    g_v[vb + (size_t)c0 * SEQ + s]       = __low2half(hv);
                    g_v[vb + (size_t)(c0 + 1) * SEQ + s] = __high2half(hv);
                }
            }
        }
    }
#undef QKV_ISSUE
}

// ---------------------------------------------------------------------------
// Kernel 2: flash attention, fp16 m16n8k16, NO online max (scores bounded:
// bias <= 0, q*k*scale ~ N(0,1); exp2 arg <= ~10 -> fp16/fp32 safe).
// 256 threads / 8 warps, BM=128 (16 rows/warp), BN=64.
// Per-lane l partial summed across iters; reduced once in epilogue.
// ---------------------------------------------------------------------------
#define TILEH (64 * LDH)
#define AT_SMEM (6 * TILEH * 2)            // 55296 B

__global__ __launch_bounds__(256) void attn_kernel(const float* __restrict__ dsc,
                                                   float* __restrict__ out) {
    extern __shared__ __half smh[];
    const uint32_t smb = s2u(smh);

    const int tid  = threadIdx.x;
    const int warp = tid >> 5;
    const int lane = tid & 31;
    const int r0   = lane >> 2;
    const int q    = lane & 3;
    const int g    = lane >> 3;
    const int lr   = lane & 7;
    const int wm   = warp * 16;

    const int bh = blockIdx.y;
    const int q0 = blockIdx.x * 128;
    const int b  = bh / HEADS;
    const int h  = bh % HEADS;

    const __half* qg = g_q + ((size_t)bh * SEQ + q0) * DH;
    const __half* kg = g_k + (size_t)bh * SEQ * DH;
    const __half* vg = g_v + (size_t)bh * DH * SEQ;

    // ---- stage Q tile (128x64 fp16), pull fragments to regs ----
#pragma unroll
    for (int i = 0; i < 4; i++) {
        int id = tid + i * 256;
        int r  = id >> 3;
        int c  = (id & 7) * 8;
        *(uint4*)&smh[r * LDH + c] = *(const uint4*)(qg + (size_t)r * DH + c);
    }
    __syncthreads();

    unsigned Qf[4][4];
    {
        uint32_t qA = smb + (uint32_t)((wm + (g & 1) * 8 + lr) * 144 + (g >> 1) * 16);
#pragma unroll
        for (int ks = 0; ks < 4; ks++)
            ldsm4(Qf[ks], qA + ks * 32);
    }
    __syncthreads();

    const int cr = tid >> 3;
    const int cc = (tid & 7) * 8;

#define AT_ISSUE(T, J) do {                                                       \
    uint32_t kb = smb + (uint32_t)((2 * (J)) * TILEH * 2);                        \
    uint32_t vb = smb + (uint32_t)((2 * (J) + 1) * TILEH * 2);                    \
    _Pragma("unroll")                                                             \
    for (int i = 0; i < 2; i++) {                                                 \
        int r = cr + i * 32;                                                      \
        cp16(kb + (uint32_t)(r * 144 + cc * 2), kg + (size_t)((T) * 64 + r) * DH + cc); \
        cp16(vb + (uint32_t)(r * 144 + cc * 2), vg + (size_t)r * SEQ + (T) * 64 + cc);  \
    } } while (0)

    AT_ISSUE(0, 0);
    asm volatile("cp.async.commit_group;");
    AT_ISSUE(1, 1);
    asm volatile("cp.async.commit_group;");

    float O[8][4];
#pragma unroll
    for (int nt = 0; nt < 8; nt++)
#pragma unroll
        for (int k = 0; k < 4; k++) O[nt][k] = 0.f;
    float l_lo = 0.f, l_hi = 0.f;   // per-lane partials; reduced in epilogue

    const uint32_t fragoff = (uint32_t)(((g & 1) * 8 + lr) * 144 + (g >> 1) * 16);

    for (int t = 0; t < 16; t++) {
        if (t < 15) asm volatile("cp.async.wait_group 1;");
        else        asm volatile("cp.async.wait_group 0;");
        __syncthreads();
        if (t + 2 < 16) {
            AT_ISSUE(t + 2, (t + 2) % 3);
            asm volatile("cp.async.commit_group;");
        }
        const int j = t % 3;
        const uint32_t kB = smb + (uint32_t)((2 * j) * TILEH * 2) + fragoff;
        const uint32_t vB = smb + (uint32_t)((2 * j + 1) * TILEH * 2) + fragoff;

        // ---- S = Q K^T  (per warp: 16 x 64; scale pre-folded into Q) ----
        float S[8][4];
#pragma unroll
        for (int nt = 0; nt < 8; nt++)
#pragma unroll
            for (int k = 0; k < 4; k++) S[nt][k] = 0.f;

#pragma unroll
        for (int ks = 0; ks < 4; ks++) {
#pragma unroll
            for (int np = 0; np < 4; np++) {
                unsigned bf[4];
                ldsm4(bf, kB + np * (uint32_t)(16 * 144) + ks * 32);
                mma_f16(S[2 * np],     Qf[ks], bf[0], bf[2]);
                mma_f16(S[2 * np + 1], Qf[ks], bf[1], bf[3]);
            }
        }

        // ---- P = exp2(S + biasL2); accumulate row-sum partials ----
        const float* b_lo = g_bL2 + (size_t)(q0 + wm + r0) * SEQ + t * 64;
        const float* b_hi = b_lo + 8 * SEQ;
#pragma unroll
        for (int nt = 0; nt < 8; nt++) {
            float2 bb0 = *(const float2*)(b_lo + nt * 8 + 2 * q);
            float2 bb1 = *(const float2*)(b_hi + nt * 8 + 2 * q);
            S[nt][0] = ex2(S[nt][0] + bb0.x);
            S[nt][1] = ex2(S[nt][1] + bb0.y);
            S[nt][2] = ex2(S[nt][2] + bb1.x);
            S[nt][3] = ex2(S[nt][3] + bb1.y);
            l_lo += S[nt][0] + S[nt][1];
            l_hi += S[nt][2] + S[nt][3];
        }

        // ---- O += P @ V ; P A-fragments packed directly from S regs ----
#pragma unroll
        for (int ks = 0; ks < 4; ks++) {
            unsigned aP[4];
            aP[0] = h2u(__floats2half2_rn(S[2 * ks][0],     S[2 * ks][1]));
            aP[1] = h2u(__floats2half2_rn(S[2 * ks][2],     S[2 * ks][3]));
            aP[2] = h2u(__floats2half2_rn(S[2 * ks + 1][0], S[2 * ks + 1][1]));
            aP[3] = h2u(__floats2half2_rn(S[2 * ks + 1][2], S[2 * ks + 1][3]));
#pragma unroll
            for (int np = 0; np < 4; np++) {
                unsigned bf[4];
                ldsm4(bf, vB + np * (uint32_t)(16 * 144) + ks * 32);
                mma_f16(O[2 * np],     aP, bf[0], bf[2]);
                mma_f16(O[2 * np + 1], aP, bf[1], bf[3]);
            }
        }
    }

    // ---- epilogue: reduce l across 4 lanes, scale, store ----
    {
        l_lo += __shfl_xor_sync(0xffffffffu, l_lo, 1);
        l_lo += __shfl_xor_sync(0xffffffffu, l_lo, 2);
        l_hi += __shfl_xor_sync(0xffffffffu, l_hi, 1);
        l_hi += __shfl_xor_sync(0xffffffffu, l_hi, 2);

        int row_lo = q0 + wm + r0;
        int row_hi = row_lo + 8;
        float sc_lo = dsc[row_lo] / l_lo;
        float sc_hi = dsc[row_hi] / l_hi;
        float* o_lo = out + ((size_t)b * SEQ + row_lo) * DIM + h * DH;
        float* o_hi = out + ((size_t)b * SEQ + row_hi) * DIM + h * DH;
#pragma unroll
        for (int nt = 0; nt < 8; nt++) {
            int c = nt * 8 + 2 * q;
            *(float2*)(o_lo + c) = make_float2(O[nt][0] * sc_lo, O[nt][1] * sc_lo);
            *(float2*)(o_hi + c) = make_float2(O[nt][2] * sc_hi, O[nt][3] * sc_hi);
        }
    }
#undef AT_ISSUE
}

// ---------------------------------------------------------------------------
extern "C" void kernel_launch(void* const* d_in, const int* in_sizes, int n_in,
                              void* d_out, int out_size) {
    const float* x    = (const float*)d_in[0];
    const float* w    = (const float*)d_in[1];
    const float* bq   = (const float*)d_in[2];
    const float* dsc  = (const float*)d_in[3];
    const float* bias = (const float*)d_in[4];
    float* out = (float*)d_out;

    cudaFuncSetAttribute(qkv_gemm, cudaFuncAttributeMaxDynamicSharedMemorySize, QKV_SMEM);
    cudaFuncSetAttribute(attn_kernel, cudaFuncAttributeMaxDynamicSharedMemorySize, AT_SMEM);

    cvt_inputs<<<CVT_BLOCKS, 256>>>(x, w, bias);
    qkv_gemm<<<dim3(18, 128), 256, QKV_SMEM>>>(bq);
    attn_kernel<<<dim3(8, BHT), 256, AT_SMEM>>>(dsc, out);
}

// round 9
// speedup vs baseline: 1.7790x; 1.0078x over previous
#include <cuda_runtime.h>
#include <cuda_fp16.h>
#include <stdint.h>
#include <math.h>

#define SEQ   1024
#define HEADS 12
#define BATCH 16
#define DH    64
#define DIM   768
#define BHT   (BATCH*HEADS)   // 192
#define LOG2E 1.4426950408889634f
#define QSCALE (0.125f * LOG2E)   // folded into stored q

// fp16 operands + attention scratch
__device__ __half g_x16[(size_t)BATCH*SEQ*DIM];
__device__ __half g_w16[(size_t)3*DIM*DIM];
__device__ float  g_bL2[(size_t)SEQ*SEQ];            // bias * log2e (fp32)
__device__ __half g_q[(size_t)BHT*SEQ*DH];           // pre-scaled by 0.125*log2e
__device__ __half g_k[(size_t)BHT*SEQ*DH];
__device__ __half g_v[(size_t)BHT*DH*SEQ];           // TRANSPOSED: [bh][chan][key]

__device__ __forceinline__ float ex2(float x) {
    float r;
    asm("ex2.approx.f32 %0, %1;" : "=f"(r) : "f"(x));
    return r;
}
__device__ __forceinline__ uint32_t s2u(const void* p) {
    return (uint32_t)__cvta_generic_to_shared(p);
}
__device__ __forceinline__ unsigned h2u(__half2 h) {
    return *(unsigned*)&h;
}
__device__ __forceinline__ void ldsm4(unsigned r[4], uint32_t a) {
    asm volatile("ldmatrix.sync.aligned.m8n8.x4.shared.b16 {%0,%1,%2,%3}, [%4];"
                 : "=r"(r[0]), "=r"(r[1]), "=r"(r[2]), "=r"(r[3]) : "r"(a));
}
__device__ __forceinline__ void mma_f16(float c[4], const unsigned a[4],
                                        unsigned b0, unsigned b1) {
    asm volatile("mma.sync.aligned.m16n8k16.row.col.f32.f16.f16.f32 "
                 "{%0,%1,%2,%3}, {%4,%5,%6,%7}, {%8,%9}, {%0,%1,%2,%3};"
                 : "+f"(c[0]), "+f"(c[1]), "+f"(c[2]), "+f"(c[3])
                 : "r"(a[0]), "r"(a[1]), "r"(a[2]), "r"(a[3]),
                   "r"(b0), "r"(b1));
}
__device__ __forceinline__ void cp16(uint32_t s, const void* g) {
    asm volatile("cp.async.ca.shared.global [%0], [%1], 16;" :: "r"(s), "l"(g));
}

// ---------------------------------------------------------------------------
// Kernel 0: one-shot conversion (x, w -> fp16; bias -> bias*log2e fp32)
// ---------------------------------------------------------------------------
#define NX (BATCH*SEQ*DIM)
#define NW (3*DIM*DIM)
#define NB (SEQ*SEQ)
#define CVT_BLOCKS ((NX+NW+NB)/4/256)

__global__ __launch_bounds__(256) void cvt_inputs(const float* __restrict__ x,
                                                  const float* __restrict__ w,
                                                  const float* __restrict__ bias) {
    size_t i = ((size_t)blockIdx.x * 256 + threadIdx.x) * 4;
    if (i < NX) {
        float4 v = *(const float4*)(x + i);
        *(__half2*)(g_x16 + i)     = __floats2half2_rn(v.x, v.y);
        *(__half2*)(g_x16 + i + 2) = __floats2half2_rn(v.z, v.w);
    } else if (i < NX + NW) {
        size_t j = i - NX;
        float4 v = *(const float4*)(w + j);
        *(__half2*)(g_w16 + j)     = __floats2half2_rn(v.x, v.y);
        *(__half2*)(g_w16 + j + 2) = __floats2half2_rn(v.z, v.w);
    } else {
        size_t j = i - NX - NW;
        float4 v = *(const float4*)(bias + j);
        *(float4*)(g_bL2 + j) = make_float4(v.x * LOG2E, v.y * LOG2E, v.z * LOG2E, v.w * LOG2E);
    }
}

// ---------------------------------------------------------------------------
// Kernel 1: qkv = x @ w^T + b  (fp16 m16n8k16, cp.async double-buffer)
// ---------------------------------------------------------------------------
#define LDH   72
#define HTILE (128 * LDH)
#define QKV_SMEM (4 * HTILE * 2)           // 73728 B

__global__ __launch_bounds__(256) void qkv_gemm(const float* __restrict__ bq) {
    extern __shared__ __half qsm[];
    const uint32_t smb = s2u(qsm);

    const int tid  = threadIdx.x;
    const int warp = tid >> 5;
    const int lane = tid & 31;
    const int r0   = lane >> 2;
    const int qq   = lane & 3;
    const int g    = lane >> 3;
    const int lr   = lane & 7;
    const int m_w  = (warp >> 1) * 32;
    const int n_w  = (warp & 1) * 64;

    float C[2][8][4];
#pragma unroll
    for (int i = 0; i < 2; i++)
#pragma unroll
        for (int j = 0; j < 8; j++)
#pragma unroll
            for (int k = 0; k < 4; k++) C[i][j][k] = 0.f;

    const __half* Ag = g_x16 + (size_t)(blockIdx.y * 128) * DIM;
    const __half* Bg = g_w16 + (size_t)(blockIdx.x * 128) * DIM;

    const int cr = tid >> 3;
    const int cc = (tid & 7) * 8;

    const uint32_t aoff = (uint32_t)((m_w + (g & 1) * 8 + lr) * 144 + (g >> 1) * 16);
    const uint32_t boff = (uint32_t)((n_w + (g & 1) * 8 + lr) * 144 + (g >> 1) * 16);

#define QKV_ISSUE(IT, BUF) do {                                                   \
    uint32_t ab = smb + (BUF) * (uint32_t)(HTILE * 2);                            \
    uint32_t bb_ = smb + (uint32_t)(2 * HTILE * 2) + (BUF) * (uint32_t)(HTILE * 2); \
    _Pragma("unroll")                                                             \
    for (int i = 0; i < 4; i++) {                                                 \
        int r = cr + i * 32;                                                      \
        cp16(ab  + (uint32_t)(r * 144 + cc * 2), Ag + (size_t)r * DIM + (IT) * 64 + cc); \
        cp16(bb_ + (uint32_t)(r * 144 + cc * 2), Bg + (size_t)r * DIM + (IT) * 64 + cc); \
    } } while (0)

    QKV_ISSUE(0, 0);
    asm volatile("cp.async.commit_group;");
    QKV_ISSUE(1, 1);
    asm volatile("cp.async.commit_group;");

    for (int it = 0; it < 12; it++) {
        if (it < 11) asm volatile("cp.async.wait_group 1;");
        else         asm volatile("cp.async.wait_group 0;");
        __syncthreads();

        const uint32_t Ab = smb + (it & 1) * (uint32_t)(HTILE * 2) + aoff;
        const uint32_t Bb = smb + (uint32_t)(2 * HTILE * 2) + (it & 1) * (uint32_t)(HTILE * 2) + boff;
#pragma unroll
        for (int ks = 0; ks < 4; ks++) {
            unsigned a[2][4];
#pragma unroll
            for (int mt = 0; mt < 2; mt++)
                ldsm4(a[mt], Ab + mt * (uint32_t)(16 * 144) + ks * 32);
#pragma unroll
            for (int np = 0; np < 4; np++) {
                unsigned bf[4];
                ldsm4(bf, Bb + np * (uint32_t)(16 * 144) + ks * 32);
#pragma unroll
                for (int mt = 0; mt < 2; mt++) {
                    mma_f16(C[mt][2 * np],     a[mt], bf[0], bf[2]);
                    mma_f16(C[mt][2 * np + 1], a[mt], bf[1], bf[3]);
                }
            }
        }
        __syncthreads();
        if (it + 2 < 12) {
            QKV_ISSUE(it + 2, it & 1);
            asm volatile("cp.async.commit_group;");
        }
    }

    // epilogue: bias add, (q: fold softmax scale), fp16 round, scatter
#pragma unroll
    for (int nt = 0; nt < 8; nt++) {
        int nb = blockIdx.x * 128 + n_w + nt * 8 + 2 * qq;
        float2 bb = *(const float2*)(bq + nb);
        int which = nb / DIM;
        int hn    = nb % DIM;
        int h     = hn >> 6;
        int c0    = hn & 63;
        float sc  = (which == 0) ? QSCALE : 1.0f;
#pragma unroll
        for (int mt = 0; mt < 2; mt++) {
#pragma unroll
            for (int half = 0; half < 2; half++) {
                int m = blockIdx.y * 128 + m_w + mt * 16 + r0 + half * 8;
                int b = m >> 10, s = m & 1023;
                __half2 hv = __floats2half2_rn((C[mt][nt][2 * half + 0] + bb.x) * sc,
                                               (C[mt][nt][2 * half + 1] + bb.y) * sc);
                size_t bh = (size_t)(b * HEADS + h);
                if (which == 0) {
                    *(__half2*)(g_q + (bh * SEQ + s) * DH + c0) = hv;
                } else if (which == 1) {
                    *(__half2*)(g_k + (bh * SEQ + s) * DH + c0) = hv;
                } else {
                    size_t vb = bh * DH * SEQ;
                    g_v[vb + (size_t)c0 * SEQ + s]       = __low2half(hv);
                    g_v[vb + (size_t)(c0 + 1) * SEQ + s] = __high2half(hv);
                }
            }
        }
    }
#undef QKV_ISSUE
}

// ---------------------------------------------------------------------------
// Kernel 2: flash attention, fp16 m16n8k16, fixed-max softmax.
// 256 threads / 8 warps, BM=128 (16 rows/warp), BN=64, 2 CTAs/SM.
// Bias prefetched into regs before QK MMA (latency hidden under HMMA).
// Row-sum l computed by an extra MMA with a CONSTANT ones B-fragment.
// ---------------------------------------------------------------------------
#define TILEH (64 * LDH)
#define AT_SMEM (6 * TILEH * 2)            // 55296 B

__global__ __launch_bounds__(256, 2) void attn_kernel(const float* __restrict__ dsc,
                                                      float* __restrict__ out) {
    extern __shared__ __half smh[];
    const uint32_t smb = s2u(smh);

    const int tid  = threadIdx.x;
    const int warp = tid >> 5;
    const int lane = tid & 31;
    const int r0   = lane >> 2;
    const int q    = lane & 3;
    const int g    = lane >> 3;
    const int lr   = lane & 7;
    const int wm   = warp * 16;

    const int bh = blockIdx.y;
    const int q0 = blockIdx.x * 128;
    const int b  = bh / HEADS;
    const int h  = bh % HEADS;

    const __half* qg = g_q + ((size_t)bh * SEQ + q0) * DH;
    const __half* kg = g_k + (size_t)bh * SEQ * DH;
    const __half* vg = g_v + (size_t)bh * DH * SEQ;

    // ---- stage Q tile (128x64 fp16), pull fragments to regs ----
#pragma unroll
    for (int i = 0; i < 4; i++) {
        int id = tid + i * 256;
        int r  = id >> 3;
        int c  = (id & 7) * 8;
        *(uint4*)&smh[r * LDH + c] = *(const uint4*)(qg + (size_t)r * DH + c);
    }
    __syncthreads();

    unsigned Qf[4][4];
    {
        uint32_t qA = smb + (uint32_t)((wm + (g & 1) * 8 + lr) * 144 + (g >> 1) * 16);
#pragma unroll
        for (int ks = 0; ks < 4; ks++)
            ldsm4(Qf[ks], qA + ks * 32);
    }
    __syncthreads();

    const int cr = tid >> 3;
    const int cc = (tid & 7) * 8;

#define AT_ISSUE(T, J) do {                                                       \
    uint32_t kb = smb + (uint32_t)((2 * (J)) * TILEH * 2);                        \
    uint32_t vb = smb + (uint32_t)((2 * (J) + 1) * TILEH * 2);                    \
    _Pragma("unroll")                                                             \
    for (int i = 0; i < 2; i++) {                                                 \
        int r = cr + i * 32;                                                      \
        cp16(kb + (uint32_t)(r * 144 + cc * 2), kg + (size_t)((T) * 64 + r) * DH + cc); \
        cp16(vb + (uint32_t)(r * 144 + cc * 2), vg + (size_t)r * SEQ + (T) * 64 + cc);  \
    } } while (0)

    AT_ISSUE(0, 0);
    asm volatile("cp.async.commit_group;");
    AT_ISSUE(1, 1);
    asm volatile("cp.async.commit_group;");

    float O[8][4];
#pragma unroll
    for (int nt = 0; nt < 8; nt++)
#pragma unroll
        for (int k = 0; k < 4; k++) O[nt][k] = 0.f;
    float Ol[4] = {0.f, 0.f, 0.f, 0.f};   // l accumulator (col 0 of ones-MMA)

    // constant ones B-fragment: local n-col 0 = 1.0 for all 16 k -> row sum
    const unsigned bl_const = (lane < 4) ? 0x3C003C00u : 0u;

    const uint32_t fragoff = (uint32_t)(((g & 1) * 8 + lr) * 144 + (g >> 1) * 16);

    for (int t = 0; t < 16; t++) {
        if (t < 15) asm volatile("cp.async.wait_group 1;");
        else        asm volatile("cp.async.wait_group 0;");
        __syncthreads();
        if (t + 2 < 16) {
            AT_ISSUE(t + 2, (t + 2) % 3);
            asm volatile("cp.async.commit_group;");
        }
        const int j = t % 3;
        const uint32_t kB = smb + (uint32_t)((2 * j) * TILEH * 2) + fragoff;
        const uint32_t vB = smb + (uint32_t)((2 * j + 1) * TILEH * 2) + fragoff;

        // ---- prefetch bias for this tile (no dependency on S -> hidden) ----
        const float* b_lo = g_bL2 + (size_t)(q0 + wm + r0) * SEQ + t * 64;
        const float* b_hi = b_lo + 8 * SEQ;
        float2 B0[8], B1[8];
#pragma unroll
        for (int nt = 0; nt < 8; nt++) {
            B0[nt] = *(const float2*)(b_lo + nt * 8 + 2 * q);
            B1[nt] = *(const float2*)(b_hi + nt * 8 + 2 * q);
        }

        // ---- S = Q K^T  (per warp: 16 x 64; scale pre-folded into Q) ----
        float S[8][4];
#pragma unroll
        for (int nt = 0; nt < 8; nt++)
#pragma unroll
            for (int k = 0; k < 4; k++) S[nt][k] = 0.f;

#pragma unroll
        for (int ks = 0; ks < 4; ks++) {
#pragma unroll
            for (int np = 0; np < 4; np++) {
                unsigned bf[4];
                ldsm4(bf, kB + np * (uint32_t)(16 * 144) + ks * 32);
                mma_f16(S[2 * np],     Qf[ks], bf[0], bf[2]);
                mma_f16(S[2 * np + 1], Qf[ks], bf[1], bf[3]);
            }
        }

        // ---- P = exp2(S + biasL2) ----
#pragma unroll
        for (int nt = 0; nt < 8; nt++) {
            S[nt][0] = ex2(S[nt][0] + B0[nt].x);
            S[nt][1] = ex2(S[nt][1] + B0[nt].y);
            S[nt][2] = ex2(S[nt][2] + B1[nt].x);
            S[nt][3] = ex2(S[nt][3] + B1[nt].y);
        }

        // ---- O += P @ V ; l += P @ ones (constant B-fragment) ----
#pragma unroll
        for (int ks = 0; ks < 4; ks++) {
            unsigned aP[4];
            aP[0] = h2u(__floats2half2_rn(S[2 * ks][0],     S[2 * ks][1]));
            aP[1] = h2u(__floats2half2_rn(S[2 * ks][2],     S[2 * ks][3]));
            aP[2] = h2u(__floats2half2_rn(S[2 * ks + 1][0], S[2 * ks + 1][1]));
            aP[3] = h2u(__floats2half2_rn(S[2 * ks + 1][2], S[2 * ks + 1][3]));
            mma_f16(Ol, aP, bl_const, bl_const);
#pragma unroll
            for (int np = 0; np < 4; np++) {
                unsigned bf[4];
                ldsm4(bf, vB + np * (uint32_t)(16 * 144) + ks * 32);
                mma_f16(O[2 * np],     aP, bf[0], bf[2]);
                mma_f16(O[2 * np + 1], aP, bf[1], bf[3]);
            }
        }
    }

    // ---- epilogue: broadcast l from q==0 lanes, scale, store ----
    {
        const unsigned src = lane & ~3u;
        float l_lo = __shfl_sync(0xffffffffu, Ol[0], src);
        float l_hi = __shfl_sync(0xffffffffu, Ol[2], src);

        int row_lo = q0 + wm + r0;
        int row_hi = row_lo + 8;
        float sc_lo = dsc[row_lo] / l_lo;
        float sc_hi = dsc[row_hi] / l_hi;
        float* o_lo = out + ((size_t)b * SEQ + row_lo) * DIM + h * DH;
        float* o_hi = out + ((size_t)b * SEQ + row_hi) * DIM + h * DH;
#pragma unroll
        for (int nt = 0; nt < 8; nt++) {
            int c = nt * 8 + 2 * q;
            *(float2*)(o_lo + c) = make_float2(O[nt][0] * sc_lo, O[nt][1] * sc_lo);
            *(float2*)(o_hi + c) = make_float2(O[nt][2] * sc_hi, O[nt][3] * sc_hi);
        }
    }
#undef AT_ISSUE
}

// ---------------------------------------------------------------------------
extern "C" void kernel_launch(void* const* d_in, const int* in_sizes, int n_in,
                              void* d_out, int out_size) {
    const float* x    = (const float*)d_in[0];
    const float* w    = (const float*)d_in[1];
    const float* bq   = (const float*)d_in[2];
    const float* dsc  = (const float*)d_in[3];
    const float* bias = (const float*)d_in[4];
    float* out = (float*)d_out;

    cudaFuncSetAttribute(qkv_gemm, cudaFuncAttributeMaxDynamicSharedMemorySize, QKV_SMEM);
    cudaFuncSetAttribute(attn_kernel, cudaFuncAttributeMaxDynamicSharedMemorySize, AT_SMEM);

    cvt_inputs<<<CVT_BLOCKS, 256>>>(x, w, bias);
    qkv_gemm<<<dim3(18, 128), 256, QKV_SMEM>>>(bq);
    attn_kernel<<<dim3(8, BHT), 256, AT_SMEM>>>(dsc, out);
}